// round 7
// baseline (speedup 1.0000x reference)
#include <cuda_runtime.h>
#include <cooperative_groups.h>
#include <cstdint>

namespace cg = cooperative_groups;

#define T_STEPS 2048
#define V_SZ    2048
#define G_SZ    24
#define K_SZ    512
#define CLUSTER_N 8
#define JPB     64              // columns of Wh per CTA
#define NCLUSTERS 12            // 12 clusters * 2 groups * 2 recs = 48
#define NBLOCKS (NCLUSTERS * CLUSTER_N)
#define THREADS_RNN 256
#define PIECE_B 64              // one producer-warp piece: 2 recs x 8 cols x 4B
#define PHASE_TX (64 * PIECE_B) // 4096 B per (group,buf) phase

// ---------------- mbarrier helpers ----------------
#define MBARRIER_INIT(addr, count) \
    asm volatile("mbarrier.init.shared.b64 [%0], %1;" :: "r"((uint32_t)(addr)), "r"((uint32_t)(count)) : "memory")

#define MBARRIER_EXPECT_TX(addr, bytes) \
    asm volatile("mbarrier.arrive.expect_tx.shared.b64 _, [%0], %1;" :: "r"((uint32_t)(addr)), "r"((uint32_t)(bytes)) : "memory")

#define MBARRIER_WAIT_PARITY(mbar_smem_addr, phase_parity) do { \
    uint32_t _mbar = (uint32_t)(mbar_smem_addr); \
    uint32_t _parity = (uint32_t)(phase_parity); \
    uint32_t _done; \
    asm volatile( \
        "{\n\t" \
        ".reg .pred p;\n\t" \
        "mbarrier.try_wait.parity.acquire.cta.shared::cta.b64 p, [%1], %2;\n\t" \
        "selp.b32 %0, 1, 0, p;\n\t" \
        "}" \
        : "=r"(_done) : "r"(_mbar), "r"(_parity) : "memory"); \
    if (!_done) { \
        asm volatile( \
            "{\n\t" \
            ".reg .pred P1;\n\t" \
            "WAIT_LOOP_%=:\n\t" \
            "mbarrier.try_wait.parity.acquire.cta.shared::cta.b64 P1, [%0], %1, 0x989680;\n\t" \
            "@P1 bra.uni WAIT_DONE_%=;\n\t" \
            "bra.uni WAIT_LOOP_%=;\n\t" \
            "WAIT_DONE_%=:\n\t" \
            "}" \
            :: "r"(_mbar), "r"(_parity) : "memory"); \
    } \
} while(0)

__device__ __forceinline__ uint32_t s2u(const void* p) {
    uint32_t a;
    asm("{ .reg .u64 t; cvta.to.shared.u64 t, %1; cvt.u32.u64 %0, t; }" : "=r"(a) : "l"(p));
    return a;
}

__device__ __forceinline__ void ffma2(unsigned long long& acc,
                                      unsigned long long h2,
                                      unsigned long long w2) {
    asm("fma.rn.f32x2 %0, %1, %2, %0;" : "+l"(acc) : "l"(h2), "l"(w2));
}

__device__ __forceinline__ unsigned long long packf2(float lo, float hi) {
    unsigned long long r;
    asm("mov.b64 %0, {%1, %2};" : "=l"(r) : "f"(lo), "f"(hi));
    return r;
}

__device__ __forceinline__ float sum2(unsigned long long acc) {
    float lo, hi;
    asm("mov.b64 {%0, %1}, %2;" : "=f"(lo), "=f"(hi) : "l"(acc));
    return lo + hi;
}

// Scratch (no cudaMalloc allowed)
__device__ float g_P[V_SZ * K_SZ];       // P = W_e @ Wx + b   (V, K)
__device__ int   g_idx[T_STEPS * G_SZ];  // idx[t,g] = perms[g, token_t]

// ---------------------------------------------------------------------------
// Kernel 1 (fused): token recovery + P = W_e @ Wx + b
// ---------------------------------------------------------------------------
__global__ void __launch_bounds__(256)
prep_kernel(const float* __restrict__ seq,
            const int* __restrict__ perms,
            const float* __restrict__ We,
            const float* __restrict__ Wx,
            const float* __restrict__ b) {
    int tid = threadIdx.x;
    int wid = tid >> 5, lane = tid & 31;

    // ---- token part: warp wid scans one one-hot row ----
    {
        int bid = blockIdx.y * gridDim.x + blockIdx.x;   // 0..255
        int row = bid * 8 + wid;                          // 0..2047
        const float4* r4 = (const float4*)(seq + (size_t)row * V_SZ) + lane * 16;
        int found = -1;
        #pragma unroll
        for (int i = 0; i < 16; i++) {
            float4 v = r4[i];
            int base = lane * 64 + i * 4;
            if (v.x > 0.5f) found = base;
            if (v.y > 0.5f) found = base + 1;
            if (v.z > 0.5f) found = base + 2;
            if (v.w > 0.5f) found = base + 3;
        }
        int tok = __reduce_max_sync(0xffffffffu, found);
        if (lane < G_SZ)
            g_idx[row * G_SZ + lane] = perms[lane * V_SZ + tok];
    }

    // ---- GEMM part ----
    __shared__ float sA[64][17];
    __shared__ float sB[16][68];
    int tx = tid & 15, ty = tid >> 4;
    int row0 = blockIdx.y * 64;
    int col0 = blockIdx.x * 64;
    float acc[4][4] = {};

    for (int kc = 0; kc < K_SZ; kc += 16) {
        {
            int v  = tid >> 2;
            int c4 = (tid & 3) * 4;
            float4 av = *(const float4*)&We[(size_t)(row0 + v) * K_SZ + kc + c4];
            sA[v][c4 + 0] = av.x; sA[v][c4 + 1] = av.y;
            sA[v][c4 + 2] = av.z; sA[v][c4 + 3] = av.w;
        }
        {
            int c  = tid >> 4;
            int k4 = (tid & 15) * 4;
            float4 bv = *(const float4*)&Wx[(size_t)(kc + c) * K_SZ + col0 + k4];
            sB[c][k4 + 0] = bv.x; sB[c][k4 + 1] = bv.y;
            sB[c][k4 + 2] = bv.z; sB[c][k4 + 3] = bv.w;
        }
        __syncthreads();
        #pragma unroll
        for (int cc = 0; cc < 16; cc++) {
            float ar[4], br[4];
            #pragma unroll
            for (int u = 0; u < 4; u++) ar[u] = sA[ty * 4 + u][cc];
            #pragma unroll
            for (int ww = 0; ww < 4; ww++) br[ww] = sB[cc][tx * 4 + ww];
            #pragma unroll
            for (int u = 0; u < 4; u++)
                #pragma unroll
                for (int ww = 0; ww < 4; ww++)
                    acc[u][ww] = fmaf(ar[u], br[ww], acc[u][ww]);
        }
        __syncthreads();
    }
    #pragma unroll
    for (int u = 0; u < 4; u++) {
        int r = row0 + ty * 4 + u;
        #pragma unroll
        for (int ww = 0; ww < 4; ww++) {
            int c = col0 + tx * 4 + ww;
            g_P[(size_t)r * K_SZ + c] = acc[u][ww] + b[c];
        }
    }
}

// ---------------------------------------------------------------------------
// Kernel 2: persistent cluster recurrence, column-split, warp-synchronous.
// Warp w of CTA rank owns output cols (rank*64 + w*8 .. +8), all 512 rows.
// Lane l: col = base + (l&7), rows [(l>>3)*128, +128). Butterfly reduce.
// Each warp ships its 64B piece (2 recs x 8 cols) to all 8 CTAs via bulk copy.
// No __syncthreads in the main loop. Two-group ping-pong retained.
// ---------------------------------------------------------------------------
__device__ __forceinline__ int tpos(int s, int dir) {
    return dir ? ((s < T_STEPS - 1) ? (T_STEPS - 2 - s) : (T_STEPS - 1)) : s;
}

struct __align__(16) SmemRNN {
    float h[2][2][64][16];        // 16384 B  [grp][buf][piece=src*8+sw][rec*8+m]
    float stage[2][2][8][16];     //  4096 B  [grp][buf][warp][rec*8+col]
    unsigned long long bar[4];    //    32 B  [grp*2+buf]
};

__global__ void __launch_bounds__(THREADS_RNN, 1) __cluster_dims__(CLUSTER_N, 1, 1)
rnn_kernel(const float* __restrict__ Wh,
           float* __restrict__ out,
           int writeHt) {
    __shared__ SmemRNN sm;
    cg::cluster_group cluster = cg::this_cluster();
    const int rank = (int)cluster.block_rank();
    const int cid  = blockIdx.x / CLUSTER_N;
    const int tid  = threadIdx.x;
    const int lane = tid & 31;
    const int w    = tid >> 5;
    const int jg   = rank * JPB;
    const int jc   = jg + w * 8 + (lane & 7);   // this lane's output column
    const int seg  = lane >> 3;                 // 0..3: row segment * 128

    const uint32_t bar_base = s2u(&sm.bar[0]);
    if (tid == 0) {
        #pragma unroll
        for (int b2 = 0; b2 < 4; b2++) MBARRIER_INIT(bar_base + b2 * 8, 1);
    }
    __syncthreads();
    if (tid == 0) {   // arm phase 0 of all four barriers
        #pragma unroll
        for (int b2 = 0; b2 < 4; b2++) MBARRIER_EXPECT_TX(bar_base + b2 * 8, PHASE_TX);
    }

    // ---- weights: 128 rows for this lane's column, packed row-pairs ----
    unsigned long long w2[64];
    {
        const float* wb = Wh + jc;
        #pragma unroll
        for (int pi = 0; pi < 16; pi++) {
            #pragma unroll
            for (int j = 0; j < 4; j++) {
                int r = seg * 128 + pi * 8 + j * 2;
                w2[pi * 4 + j] = packf2(wb[(size_t)r * K_SZ],
                                        wb[(size_t)(r + 1) * K_SZ]);
            }
        }
    }
    // zero all h buffers
    for (int i = tid; i < 2 * 2 * 64 * 16; i += THREADS_RNN)
        (&sm.h[0][0][0][0])[i] = 0.f;

    // ---- x in registers (lanes 16..23 hold col w*8 + (lane-16)) ----
    const bool xlane = (lane >= 16 && lane < 24);
    const int  xcol  = jg + w * 8 + (lane - 16);
    float xF[2] = {0.f, 0.f}, xR[2] = {0.f, 0.f};
    int   tF[2] = {0, 0},     tR[2] = {0, 0};
    if (xlane) {
        #pragma unroll
        for (int g = 0; g < 2; g++) {
            int gg = cid * 2 + g;
            xF[g] = g_P[(size_t)g_idx[0 * G_SZ + gg] * K_SZ + xcol];
            xR[g] = g_P[(size_t)g_idx[(T_STEPS - 2) * G_SZ + gg] * K_SZ + xcol];
            tF[g] = g_idx[1 * G_SZ + gg];
            tR[g] = g_idx[(T_STEPS - 3) * G_SZ + gg];
        }
    }
    __syncthreads();
    cluster.sync();   // barriers armed cluster-wide before any copies fly

    // DSMEM destinations: lane d (d = lane&7) handles destination CTA d
    const uint32_t my_h     = s2u(&sm.h[0][0][0][0]);
    const uint32_t my_stage = s2u(&sm.stage[0][0][0][0]);
    uint32_t dst_h, dst_bar;
    {
        int d = lane & 7;
        asm("mapa.shared::cluster.u32 %0, %1, %2;" : "=r"(dst_h)   : "r"(my_h),     "r"(d));
        asm("mapa.shared::cluster.u32 %0, %1, %2;" : "=r"(dst_bar) : "r"(bar_base), "r"(d));
    }

    const size_t hb0 = (size_t)T_STEPS * G_SZ * 2 * K_SZ;
    int p = 0;
    for (int s = 0; s < T_STEPS; s++) {
        const bool last = (s == T_STEPS - 1);
        const int np = p ^ 1;
        const int wpar = ((s >> 1) + 1 - (s & 1)) & 1;

        #pragma unroll
        for (int g = 0; g < 2; g++) {
            const int gg = cid * 2 + g;

            // ---- issue x gathers for step s+1 (hidden under mainloop) ----
            float xFn = 0.f, xRn = 0.f;
            if (xlane && !last) {
                xFn = g_P[(size_t)tF[g] * K_SZ + xcol];
                xRn = g_P[(size_t)tR[g] * K_SZ + xcol];
            }

            // ---- wait for full h of this group (4KB = 64 pieces) ----
            const uint32_t mybar = bar_base + (uint32_t)((g * 2 + p) * 8);
            if (s > 0) {
                MBARRIER_WAIT_PARITY(mybar, wpar);
                if (tid == 0 && s + 2 < T_STEPS)
                    MBARRIER_EXPECT_TX(mybar, PHASE_TX);   // re-arm next phase
            }

            // ---- mainloop: 64 LDS.128 + 128 FFMA2, no syncs ----
            const float* hb = &sm.h[g][p][seg * 16][0];
            unsigned long long acc0 = 0ull, acc1 = 0ull;
            #pragma unroll
            for (int pi = 0; pi < 16; pi++) {
                const float* pb = hb + pi * 16;
                ulonglong2 Ha = *(const ulonglong2*)(pb);       // rec0 m0..3
                ulonglong2 Hb = *(const ulonglong2*)(pb + 4);   // rec0 m4..7
                ulonglong2 Hc = *(const ulonglong2*)(pb + 8);   // rec1 m0..3
                ulonglong2 Hd = *(const ulonglong2*)(pb + 12);  // rec1 m4..7
                ffma2(acc0, Ha.x, w2[pi * 4 + 0]);  ffma2(acc0, Ha.y, w2[pi * 4 + 1]);
                ffma2(acc0, Hb.x, w2[pi * 4 + 2]);  ffma2(acc0, Hb.y, w2[pi * 4 + 3]);
                ffma2(acc1, Hc.x, w2[pi * 4 + 0]);  ffma2(acc1, Hc.y, w2[pi * 4 + 1]);
                ffma2(acc1, Hd.x, w2[pi * 4 + 2]);  ffma2(acc1, Hd.y, w2[pi * 4 + 3]);
            }
            float a0 = sum2(acc0), a1 = sum2(acc1);
            a0 += __shfl_xor_sync(0xffffffffu, a0, 8);
            a0 += __shfl_xor_sync(0xffffffffu, a0, 16);
            a1 += __shfl_xor_sync(0xffffffffu, a1, 8);
            a1 += __shfl_xor_sync(0xffffffffu, a1, 16);

            float sxF = __shfl_sync(0xffffffffu, xF[g], 16 + (lane & 7));
            float sxR = __shfl_sync(0xffffffffu, xR[g], 16 + (lane & 7));

            float v0 = 0.f, v1 = 0.f;
            if (lane < 8) {
                v0 = tanhf(a0 + sxF);
                v1 = tanhf(a1 + sxR);
                if (!last) {
                    sm.stage[g][p][w][lane]     = v0;
                    sm.stage[g][p][w][8 + lane] = v1;
                }
            }
            __syncwarp();
            if (lane < 8 && !last) {
                asm volatile("fence.proxy.async.shared::cta;" ::: "memory");
                uint32_t src = my_stage + (uint32_t)(((g * 2 + p) * 8 + w) * PIECE_B);
                uint32_t dst = dst_h + (uint32_t)(((g * 2 + np) * 64 + rank * 8 + w) * PIECE_B);
                uint32_t db  = dst_bar + (uint32_t)((g * 2 + np) * 8);
                asm volatile(
                    "cp.async.bulk.shared::cluster.shared::cta.mbarrier::complete_tx::bytes "
                    "[%0], [%1], %2, [%3];"
                    :: "r"(dst), "r"(src), "r"(PIECE_B), "r"(db) : "memory");
            }

            // ---- global stores (off critical path) ----
            if (lane < 8) {
                int tt0 = tpos(s, 0), tt1 = tpos(s, 1);
                out[((size_t)tt0 * G_SZ + gg) * (2 * K_SZ) + jc]        = v0;
                out[((size_t)tt1 * G_SZ + gg) * (2 * K_SZ) + K_SZ + jc] = v1;
                if (last && writeHt) {
                    out[hb0 + (size_t)gg * (2 * K_SZ) + jc]        = v0;
                    out[hb0 + (size_t)gg * (2 * K_SZ) + K_SZ + jc] = v1;
                }
            } else if (xlane) {
                xF[g] = xFn;  xR[g] = xRn;
                if (s + 2 < T_STEPS) {
                    tF[g] = g_idx[tpos(s + 2, 0) * G_SZ + gg];
                    tR[g] = g_idx[tpos(s + 2, 1) * G_SZ + gg];
                }
            }
        }
        p = np;
    }
    cluster.sync();   // no CTA exits while peer copies may be in flight
}

// ---------------------------------------------------------------------------
extern "C" void kernel_launch(void* const* d_in, const int* in_sizes, int n_in,
                              void* d_out, int out_size) {
    const float* seq   = (const float*)d_in[0];  // (T, V)
    const int*   perms = (const int*)  d_in[1];  // (G, V)
    const float* We    = (const float*)d_in[2];  // (V, K)
    const float* Wx    = (const float*)d_in[3];  // (K, K)
    const float* Wh    = (const float*)d_in[4];  // (K, K)
    const float* b     = (const float*)d_in[5];  // (K,)
    float* out = (float*)d_out;
    (void)in_sizes; (void)n_in;

    long long need = (long long)T_STEPS * G_SZ * 2 * K_SZ + (long long)G_SZ * 2 * K_SZ;
    int writeHt = ((long long)out_size >= need) ? 1 : 0;

    dim3 ggrid(K_SZ / 64, V_SZ / 64);   // (8, 32) = 256 blocks
    prep_kernel<<<ggrid, 256>>>(seq, perms, We, Wx, b);
    rnn_kernel<<<NBLOCKS, THREADS_RNN>>>(Wh, out, writeHt);
}

// round 8
// speedup vs baseline: 1.1664x; 1.1664x over previous
#include <cuda_runtime.h>
#include <cooperative_groups.h>
#include <cstdint>

namespace cg = cooperative_groups;

#define T_STEPS 2048
#define V_SZ    2048
#define G_SZ    24
#define K_SZ    512
#define CLUSTER_N 8
#define JPB     64              // columns of Wh per CTA
#define NCLUSTERS 12            // 12 clusters * 2 groups * 2 recs = 48
#define NBLOCKS (NCLUSTERS * CLUSTER_N)
#define THREADS_RNN 256
#define SLICE_B 512             // one CTA's h contribution per group: 2 recs x 64 cols x 4B
#define PHASE_TX ((CLUSTER_N - 1) * SLICE_B)   // 3584 B remote per (group,buf) phase

// ---------------- mbarrier helpers ----------------
#define MBARRIER_INIT(addr, count) \
    asm volatile("mbarrier.init.shared.b64 [%0], %1;" :: "r"((uint32_t)(addr)), "r"((uint32_t)(count)) : "memory")

#define MBARRIER_EXPECT_TX(addr, bytes) \
    asm volatile("mbarrier.arrive.expect_tx.shared.b64 _, [%0], %1;" :: "r"((uint32_t)(addr)), "r"((uint32_t)(bytes)) : "memory")

#define MBARRIER_WAIT_PARITY(mbar_smem_addr, phase_parity) do { \
    uint32_t _mbar = (uint32_t)(mbar_smem_addr); \
    uint32_t _parity = (uint32_t)(phase_parity); \
    uint32_t _done; \
    asm volatile( \
        "{\n\t" \
        ".reg .pred p;\n\t" \
        "mbarrier.try_wait.parity.acquire.cta.shared::cta.b64 p, [%1], %2;\n\t" \
        "selp.b32 %0, 1, 0, p;\n\t" \
        "}" \
        : "=r"(_done) : "r"(_mbar), "r"(_parity) : "memory"); \
    if (!_done) { \
        asm volatile( \
            "{\n\t" \
            ".reg .pred P1;\n\t" \
            "WAIT_LOOP_%=:\n\t" \
            "mbarrier.try_wait.parity.acquire.cta.shared::cta.b64 P1, [%0], %1, 0x989680;\n\t" \
            "@P1 bra.uni WAIT_DONE_%=;\n\t" \
            "bra.uni WAIT_LOOP_%=;\n\t" \
            "WAIT_DONE_%=:\n\t" \
            "}" \
            :: "r"(_mbar), "r"(_parity) : "memory"); \
    } \
} while(0)

__device__ __forceinline__ uint32_t s2u(const void* p) {
    uint32_t a;
    asm("{ .reg .u64 t; cvta.to.shared.u64 t, %1; cvt.u32.u64 %0, t; }" : "=r"(a) : "l"(p));
    return a;
}

__device__ __forceinline__ void ffma2(unsigned long long& acc,
                                      unsigned long long h2,
                                      unsigned long long w2) {
    asm("fma.rn.f32x2 %0, %1, %2, %0;" : "+l"(acc) : "l"(h2), "l"(w2));
}

__device__ __forceinline__ unsigned long long packf2(float lo, float hi) {
    unsigned long long r;
    asm("mov.b64 %0, {%1, %2};" : "=l"(r) : "f"(lo), "f"(hi));
    return r;
}

__device__ __forceinline__ float sum2(unsigned long long acc) {
    float lo, hi;
    asm("mov.b64 {%0, %1}, %2;" : "=f"(lo), "=f"(hi) : "l"(acc));
    return lo + hi;
}

// Scratch (no cudaMalloc allowed)
__device__ float g_P[V_SZ * K_SZ];       // P = W_e @ Wx + b   (V, K)
__device__ int   g_idx[T_STEPS * G_SZ];  // idx[t,g] = perms[g, token_t]

// ---------------------------------------------------------------------------
// Kernel 1 (fused): token recovery + P = W_e @ Wx + b
// ---------------------------------------------------------------------------
__global__ void __launch_bounds__(256)
prep_kernel(const float* __restrict__ seq,
            const int* __restrict__ perms,
            const float* __restrict__ We,
            const float* __restrict__ Wx,
            const float* __restrict__ b) {
    int tid = threadIdx.x;
    int wid = tid >> 5, lane = tid & 31;

    // ---- token part: warp wid scans one one-hot row ----
    {
        int bid = blockIdx.y * gridDim.x + blockIdx.x;   // 0..255
        int row = bid * 8 + wid;                          // 0..2047
        const float4* r4 = (const float4*)(seq + (size_t)row * V_SZ) + lane * 16;
        int found = -1;
        #pragma unroll
        for (int i = 0; i < 16; i++) {
            float4 v = r4[i];
            int base = lane * 64 + i * 4;
            if (v.x > 0.5f) found = base;
            if (v.y > 0.5f) found = base + 1;
            if (v.z > 0.5f) found = base + 2;
            if (v.w > 0.5f) found = base + 3;
        }
        int tok = __reduce_max_sync(0xffffffffu, found);
        if (lane < G_SZ)
            g_idx[row * G_SZ + lane] = perms[lane * V_SZ + tok];
    }

    // ---- GEMM part ----
    __shared__ float sA[64][17];
    __shared__ float sB[16][68];
    int tx = tid & 15, ty = tid >> 4;
    int row0 = blockIdx.y * 64;
    int col0 = blockIdx.x * 64;
    float acc[4][4] = {};

    for (int kc = 0; kc < K_SZ; kc += 16) {
        {
            int v  = tid >> 2;
            int c4 = (tid & 3) * 4;
            float4 av = *(const float4*)&We[(size_t)(row0 + v) * K_SZ + kc + c4];
            sA[v][c4 + 0] = av.x; sA[v][c4 + 1] = av.y;
            sA[v][c4 + 2] = av.z; sA[v][c4 + 3] = av.w;
        }
        {
            int c  = tid >> 4;
            int k4 = (tid & 15) * 4;
            float4 bv = *(const float4*)&Wx[(size_t)(kc + c) * K_SZ + col0 + k4];
            sB[c][k4 + 0] = bv.x; sB[c][k4 + 1] = bv.y;
            sB[c][k4 + 2] = bv.z; sB[c][k4 + 3] = bv.w;
        }
        __syncthreads();
        #pragma unroll
        for (int cc = 0; cc < 16; cc++) {
            float ar[4], br[4];
            #pragma unroll
            for (int u = 0; u < 4; u++) ar[u] = sA[ty * 4 + u][cc];
            #pragma unroll
            for (int ww = 0; ww < 4; ww++) br[ww] = sB[cc][tx * 4 + ww];
            #pragma unroll
            for (int u = 0; u < 4; u++)
                #pragma unroll
                for (int ww = 0; ww < 4; ww++)
                    acc[u][ww] = fmaf(ar[u], br[ww], acc[u][ww]);
        }
        __syncthreads();
    }
    #pragma unroll
    for (int u = 0; u < 4; u++) {
        int r = row0 + ty * 4 + u;
        #pragma unroll
        for (int ww = 0; ww < 4; ww++) {
            int c = col0 + tx * 4 + ww;
            g_P[(size_t)r * K_SZ + c] = acc[u][ww] + b[c];
        }
    }
}

// ---------------------------------------------------------------------------
// Kernel 2: persistent cluster recurrence.
// Column-split compute: warp w owns 8 output cols, lane (seg, c) covers rows
// [seg*128, +128) of one col; butterfly-shuffle reduce. One __syncthreads per
// slot; 7 consolidated 512B bulk copies per slot sourced from the local h slice.
// Two-group ping-pong (copy latency hidden by the other group's compute).
// ---------------------------------------------------------------------------
__device__ __forceinline__ int tpos(int s, int dir) {
    return dir ? ((s < T_STEPS - 1) ? (T_STEPS - 2 - s) : (T_STEPS - 1)) : s;
}

struct __align__(16) SmemRNN {
    float h[2][2][CLUSTER_N][2][64];   // 16384 B [grp][buf][src][rec][col]
    unsigned long long bar[4];         //    32 B [grp*2+buf]
};

__global__ void __launch_bounds__(THREADS_RNN, 1) __cluster_dims__(CLUSTER_N, 1, 1)
rnn_kernel(const float* __restrict__ Wh,
           float* __restrict__ out,
           int writeHt) {
    __shared__ SmemRNN sm;
    cg::cluster_group cluster = cg::this_cluster();
    const int rank = (int)cluster.block_rank();
    const int cid  = blockIdx.x / CLUSTER_N;
    const int tid  = threadIdx.x;
    const int lane = tid & 31;
    const int w    = tid >> 5;
    const int jg   = rank * JPB;
    const int jc   = jg + w * 8 + (lane & 7);   // this lane's output column
    const int seg  = lane >> 3;                 // row segment: rows [seg*128, +128)

    const uint32_t bar_base = s2u(&sm.bar[0]);
    if (tid == 0) {
        #pragma unroll
        for (int b2 = 0; b2 < 4; b2++) MBARRIER_INIT(bar_base + b2 * 8, 1);
    }
    __syncthreads();
    if (tid == 0) {
        #pragma unroll
        for (int b2 = 0; b2 < 4; b2++) MBARRIER_EXPECT_TX(bar_base + b2 * 8, PHASE_TX);
    }

    // ---- weights: rows [seg*128, +128) of column jc, packed row-pairs ----
    // Ordering matches the mainloop: block k (64 rows), then pair m.
    unsigned long long w2[64];
    {
        const float* wb = Wh + jc;
        #pragma unroll
        for (int k = 0; k < 2; k++)
            #pragma unroll
            for (int m = 0; m < 32; m++) {
                int r = seg * 128 + k * 64 + 2 * m;
                w2[k * 32 + m] = packf2(wb[(size_t)r * K_SZ],
                                        wb[(size_t)(r + 1) * K_SZ]);
            }
    }
    // zero all h buffers
    for (int i = tid; i < 2 * 2 * CLUSTER_N * 2 * 64; i += THREADS_RNN)
        (&sm.h[0][0][0][0][0])[i] = 0.f;

    // ---- x in registers: lanes 16..23 hold col w*8+(lane-16) for both dirs ----
    const bool xlane = (lane >= 16 && lane < 24);
    const int  xcol  = jg + w * 8 + (lane - 16);
    float xF[2] = {0.f, 0.f}, xR[2] = {0.f, 0.f};
    int   tF[2] = {0, 0},     tR[2] = {0, 0};
    if (xlane) {
        #pragma unroll
        for (int g = 0; g < 2; g++) {
            int gg = cid * 2 + g;
            xF[g] = g_P[(size_t)g_idx[0 * G_SZ + gg] * K_SZ + xcol];
            xR[g] = g_P[(size_t)g_idx[(T_STEPS - 2) * G_SZ + gg] * K_SZ + xcol];
            tF[g] = g_idx[1 * G_SZ + gg];
            tR[g] = g_idx[(T_STEPS - 3) * G_SZ + gg];
        }
    }
    __syncthreads();
    cluster.sync();   // barriers armed cluster-wide before any copies fly

    // issuer threads (tid 0..6): destination rank skipping self
    uint32_t rem_h_t = 0, rem_bar_t = 0;
    const uint32_t my_h = s2u(&sm.h[0][0][0][0][0]);
    if (tid < CLUSTER_N - 1) {
        int dst = tid + (tid >= rank ? 1 : 0);
        asm("mapa.shared::cluster.u32 %0, %1, %2;" : "=r"(rem_h_t)   : "r"(my_h),     "r"(dst));
        asm("mapa.shared::cluster.u32 %0, %1, %2;" : "=r"(rem_bar_t) : "r"(bar_base), "r"(dst));
    }

    const size_t hb0 = (size_t)T_STEPS * G_SZ * 2 * K_SZ;
    int p = 0;
    for (int s = 0; s < T_STEPS; s++) {
        const bool last = (s == T_STEPS - 1);
        const int np = p ^ 1;
        const int wpar = ((s >> 1) + 1 - (s & 1)) & 1;

        #pragma unroll
        for (int g = 0; g < 2; g++) {
            const int gg = cid * 2 + g;

            // ---- issue x gathers for step s+1 (hidden under mainloop) ----
            float xFn = 0.f, xRn = 0.f;
            if (xlane && !last) {
                xFn = g_P[(size_t)tF[g] * K_SZ + xcol];
                xRn = g_P[(size_t)tR[g] * K_SZ + xcol];
            }

            // ---- wait for this group's h (remote 3584B); re-arm next phase ----
            const uint32_t mybar = bar_base + (uint32_t)((g * 2 + p) * 8);
            if (s > 0) {
                MBARRIER_WAIT_PARITY(mybar, wpar);
                if (tid == 0 && s + 2 < T_STEPS)
                    MBARRIER_EXPECT_TX(mybar, PHASE_TX);
            }

            // ---- mainloop: rows [seg*128, +128) of col jc, both recs ----
            const float* hbase = &sm.h[g][p][2 * seg][0][0];  // 2 src blocks: [2][2][64]
            unsigned long long a0e = 0ull, a0o = 0ull, a1e = 0ull, a1o = 0ull;
            #pragma unroll
            for (int k = 0; k < 2; k++) {
                const float* b0 = hbase + k * 128;        // rec0: 64 floats
                const float* b1 = b0 + 64;                // rec1: 64 floats
                #pragma unroll
                for (int m = 0; m < 16; m++) {            // 4 floats per load
                    ulonglong2 H0 = *(const ulonglong2*)(b0 + 4 * m);
                    ulonglong2 H1 = *(const ulonglong2*)(b1 + 4 * m);
                    ffma2(a0e, H0.x, w2[k * 32 + 2 * m]);
                    ffma2(a0o, H0.y, w2[k * 32 + 2 * m + 1]);
                    ffma2(a1e, H1.x, w2[k * 32 + 2 * m]);
                    ffma2(a1o, H1.y, w2[k * 32 + 2 * m + 1]);
                }
            }
            float a0 = sum2(a0e) + sum2(a0o);
            float a1 = sum2(a1e) + sum2(a1o);
            a0 += __shfl_xor_sync(0xffffffffu, a0, 8);
            a0 += __shfl_xor_sync(0xffffffffu, a0, 16);
            a1 += __shfl_xor_sync(0xffffffffu, a1, 8);
            a1 += __shfl_xor_sync(0xffffffffu, a1, 16);

            float sxF = __shfl_sync(0xffffffffu, xF[g], 16 + (lane & 7));
            float sxR = __shfl_sync(0xffffffffu, xR[g], 16 + (lane & 7));

            float v0 = 0.f, v1 = 0.f;
            if (lane < 8) {
                v0 = tanhf(a0 + sxF);
                v1 = tanhf(a1 + sxR);
                if (!last) {
                    // write local h slice directly (copy source + local consume)
                    sm.h[g][np][rank][0][w * 8 + lane] = v0;
                    sm.h[g][np][rank][1][w * 8 + lane] = v1;
                    asm volatile("fence.proxy.async.shared::cta;" ::: "memory");
                }
            }
            __syncthreads();

            // ---- 7 consolidated remote copies (512B each) ----
            if (!last && tid < CLUSTER_N - 1) {
                uint32_t off = (uint32_t)(((g * 2 + np) * CLUSTER_N + rank) * SLICE_B);
                uint32_t rb  = rem_bar_t + (uint32_t)((g * 2 + np) * 8);
                asm volatile(
                    "cp.async.bulk.shared::cluster.shared::cta.mbarrier::complete_tx::bytes "
                    "[%0], [%1], %2, [%3];"
                    :: "r"(rem_h_t + off), "r"(my_h + off), "r"(SLICE_B), "r"(rb) : "memory");
            }

            // ---- tail: global out stores + x register rotation ----
            if (lane < 8) {
                int tt0 = tpos(s, 0), tt1 = tpos(s, 1);
                out[((size_t)tt0 * G_SZ + gg) * (2 * K_SZ) + jc]        = v0;
                out[((size_t)tt1 * G_SZ + gg) * (2 * K_SZ) + K_SZ + jc] = v1;
                if (last && writeHt) {
                    out[hb0 + (size_t)gg * (2 * K_SZ) + jc]        = v0;
                    out[hb0 + (size_t)gg * (2 * K_SZ) + K_SZ + jc] = v1;
                }
            } else if (xlane) {
                xF[g] = xFn;  xR[g] = xRn;
                if (s + 2 < T_STEPS) {
                    tF[g] = g_idx[tpos(s + 2, 0) * G_SZ + gg];
                    tR[g] = g_idx[tpos(s + 2, 1) * G_SZ + gg];
                }
            }
        }
        p = np;
    }
    cluster.sync();   // no CTA exits while peer copies may be in flight
}

// ---------------------------------------------------------------------------
extern "C" void kernel_launch(void* const* d_in, const int* in_sizes, int n_in,
                              void* d_out, int out_size) {
    const float* seq   = (const float*)d_in[0];  // (T, V)
    const int*   perms = (const int*)  d_in[1];  // (G, V)
    const float* We    = (const float*)d_in[2];  // (V, K)
    const float* Wx    = (const float*)d_in[3];  // (K, K)
    const float* Wh    = (const float*)d_in[4];  // (K, K)
    const float* b     = (const float*)d_in[5];  // (K,)
    float* out = (float*)d_out;
    (void)in_sizes; (void)n_in;

    long long need = (long long)T_STEPS * G_SZ * 2 * K_SZ + (long long)G_SZ * 2 * K_SZ;
    int writeHt = ((long long)out_size >= need) ? 1 : 0;

    dim3 ggrid(K_SZ / 64, V_SZ / 64);   // (8, 32) = 256 blocks
    prep_kernel<<<ggrid, 256>>>(seq, perms, We, Wx, b);
    rnn_kernel<<<NBLOCKS, THREADS_RNN>>>(Wh, out, writeHt);
}

// round 9
// speedup vs baseline: 1.7599x; 1.5089x over previous
#include <cuda_runtime.h>
#include <cooperative_groups.h>
#include <cstdint>

namespace cg = cooperative_groups;

#define T_STEPS 2048
#define V_SZ    2048
#define G_SZ    24
#define K_SZ    512
#define CLUSTER_N 8
#define JPB     64              // columns of Wh per CTA
#define NCLUSTERS 12            // 12 clusters * 2 groups * 2 recs = 48
#define NBLOCKS (NCLUSTERS * CLUSTER_N)
#define THREADS_RNN 256
#define BLK_F   132             // padded source block: 128 data floats + 4 pad
#define SLICE_B 512             // copied bytes per (src CTA, group): 2 recs x 64 cols
#define PHASE_TX ((CLUSTER_N - 1) * SLICE_B)   // 3584 B remote per (group,buf) phase

// ---------------- mbarrier helpers ----------------
#define MBARRIER_INIT(addr, count) \
    asm volatile("mbarrier.init.shared.b64 [%0], %1;" :: "r"((uint32_t)(addr)), "r"((uint32_t)(count)) : "memory")

#define MBARRIER_EXPECT_TX(addr, bytes) \
    asm volatile("mbarrier.arrive.expect_tx.shared.b64 _, [%0], %1;" :: "r"((uint32_t)(addr)), "r"((uint32_t)(bytes)) : "memory")

#define MBARRIER_WAIT_PARITY(mbar_smem_addr, phase_parity) do { \
    uint32_t _mbar = (uint32_t)(mbar_smem_addr); \
    uint32_t _parity = (uint32_t)(phase_parity); \
    uint32_t _done; \
    asm volatile( \
        "{\n\t" \
        ".reg .pred p;\n\t" \
        "mbarrier.try_wait.parity.acquire.cta.shared::cta.b64 p, [%1], %2;\n\t" \
        "selp.b32 %0, 1, 0, p;\n\t" \
        "}" \
        : "=r"(_done) : "r"(_mbar), "r"(_parity) : "memory"); \
    if (!_done) { \
        asm volatile( \
            "{\n\t" \
            ".reg .pred P1;\n\t" \
            "WAIT_LOOP_%=:\n\t" \
            "mbarrier.try_wait.parity.acquire.cta.shared::cta.b64 P1, [%0], %1, 0x989680;\n\t" \
            "@P1 bra.uni WAIT_DONE_%=;\n\t" \
            "bra.uni WAIT_LOOP_%=;\n\t" \
            "WAIT_DONE_%=:\n\t" \
            "}" \
            :: "r"(_mbar), "r"(_parity) : "memory"); \
    } \
} while(0)

__device__ __forceinline__ uint32_t s2u(const void* p) {
    uint32_t a;
    asm("{ .reg .u64 t; cvta.to.shared.u64 t, %1; cvt.u32.u64 %0, t; }" : "=r"(a) : "l"(p));
    return a;
}

__device__ __forceinline__ void ffma2(unsigned long long& acc,
                                      unsigned long long h2,
                                      unsigned long long w2) {
    asm("fma.rn.f32x2 %0, %1, %2, %0;" : "+l"(acc) : "l"(h2), "l"(w2));
}

__device__ __forceinline__ unsigned long long packf2(float lo, float hi) {
    unsigned long long r;
    asm("mov.b64 %0, {%1, %2};" : "=l"(r) : "f"(lo), "f"(hi));
    return r;
}

__device__ __forceinline__ float sum2(unsigned long long acc) {
    float lo, hi;
    asm("mov.b64 {%0, %1}, %2;" : "=f"(lo), "=f"(hi) : "l"(acc));
    return lo + hi;
}

// Scratch (no cudaMalloc allowed)
__device__ float g_P[V_SZ * K_SZ];       // P = W_e @ Wx + b   (V, K)
__device__ int   g_idx[T_STEPS * G_SZ];  // idx[t,g] = perms[g, token_t]

// ---------------------------------------------------------------------------
// Kernel 1 (fused): token recovery + P = W_e @ Wx + b
// ---------------------------------------------------------------------------
__global__ void __launch_bounds__(256)
prep_kernel(const float* __restrict__ seq,
            const int* __restrict__ perms,
            const float* __restrict__ We,
            const float* __restrict__ Wx,
            const float* __restrict__ b) {
    int tid = threadIdx.x;
    int wid = tid >> 5, lane = tid & 31;

    // ---- token part: warp wid scans one one-hot row ----
    {
        int bid = blockIdx.y * gridDim.x + blockIdx.x;   // 0..255
        int row = bid * 8 + wid;                          // 0..2047
        const float4* r4 = (const float4*)(seq + (size_t)row * V_SZ) + lane * 16;
        int found = -1;
        #pragma unroll
        for (int i = 0; i < 16; i++) {
            float4 v = r4[i];
            int base = lane * 64 + i * 4;
            if (v.x > 0.5f) found = base;
            if (v.y > 0.5f) found = base + 1;
            if (v.z > 0.5f) found = base + 2;
            if (v.w > 0.5f) found = base + 3;
        }
        int tok = __reduce_max_sync(0xffffffffu, found);
        if (lane < G_SZ)
            g_idx[row * G_SZ + lane] = perms[lane * V_SZ + tok];
    }

    // ---- GEMM part ----
    __shared__ float sA[64][17];
    __shared__ float sB[16][68];
    int tx = tid & 15, ty = tid >> 4;
    int row0 = blockIdx.y * 64;
    int col0 = blockIdx.x * 64;
    float acc[4][4] = {};

    for (int kc = 0; kc < K_SZ; kc += 16) {
        {
            int v  = tid >> 2;
            int c4 = (tid & 3) * 4;
            float4 av = *(const float4*)&We[(size_t)(row0 + v) * K_SZ + kc + c4];
            sA[v][c4 + 0] = av.x; sA[v][c4 + 1] = av.y;
            sA[v][c4 + 2] = av.z; sA[v][c4 + 3] = av.w;
        }
        {
            int c  = tid >> 4;
            int k4 = (tid & 15) * 4;
            float4 bv = *(const float4*)&Wx[(size_t)(kc + c) * K_SZ + col0 + k4];
            sB[c][k4 + 0] = bv.x; sB[c][k4 + 1] = bv.y;
            sB[c][k4 + 2] = bv.z; sB[c][k4 + 3] = bv.w;
        }
        __syncthreads();
        #pragma unroll
        for (int cc = 0; cc < 16; cc++) {
            float ar[4], br[4];
            #pragma unroll
            for (int u = 0; u < 4; u++) ar[u] = sA[ty * 4 + u][cc];
            #pragma unroll
            for (int ww = 0; ww < 4; ww++) br[ww] = sB[cc][tx * 4 + ww];
            #pragma unroll
            for (int u = 0; u < 4; u++)
                #pragma unroll
                for (int ww = 0; ww < 4; ww++)
                    acc[u][ww] = fmaf(ar[u], br[ww], acc[u][ww]);
        }
        __syncthreads();
    }
    #pragma unroll
    for (int u = 0; u < 4; u++) {
        int r = row0 + ty * 4 + u;
        #pragma unroll
        for (int ww = 0; ww < 4; ww++) {
            int c = col0 + tx * 4 + ww;
            g_P[(size_t)r * K_SZ + c] = acc[u][ww] + b[c];
        }
    }
}

// ---------------------------------------------------------------------------
// Kernel 2: persistent cluster recurrence, column-split, PADDED h layout.
// h source block per src CTA: [rec0 x64 | rec1 x64 | pad x4] = 132 floats,
// so the 4 row-segments of a warp read banks {0,8,16,24} — conflict-free.
// Warp w owns 8 output cols; lane (seg,c) covers rows [seg*128,+128) of col c.
// Butterfly-shuffle reduce; one __syncthreads per slot; 7x512B bulk copies.
// Two-group ping-pong hides copy latency.
// ---------------------------------------------------------------------------
__device__ __forceinline__ int tpos(int s, int dir) {
    return dir ? ((s < T_STEPS - 1) ? (T_STEPS - 2 - s) : (T_STEPS - 1)) : s;
}

struct __align__(16) SmemRNN {
    float h[2][2][CLUSTER_N][BLK_F];   // 16896 B [grp][buf][src][132]
    unsigned long long bar[4];         //    32 B [grp*2+buf]
};

__global__ void __launch_bounds__(THREADS_RNN, 1) __cluster_dims__(CLUSTER_N, 1, 1)
rnn_kernel(const float* __restrict__ Wh,
           float* __restrict__ out,
           int writeHt) {
    __shared__ SmemRNN sm;
    cg::cluster_group cluster = cg::this_cluster();
    const int rank = (int)cluster.block_rank();
    const int cid  = blockIdx.x / CLUSTER_N;
    const int tid  = threadIdx.x;
    const int lane = tid & 31;
    const int w    = tid >> 5;
    const int jg   = rank * JPB;
    const int jc   = jg + w * 8 + (lane & 7);   // this lane's output column
    const int seg  = lane >> 3;                 // row segment: rows [seg*128, +128)

    const uint32_t bar_base = s2u(&sm.bar[0]);
    if (tid == 0) {
        #pragma unroll
        for (int b2 = 0; b2 < 4; b2++) MBARRIER_INIT(bar_base + b2 * 8, 1);
    }
    __syncthreads();
    if (tid == 0) {
        #pragma unroll
        for (int b2 = 0; b2 < 4; b2++) MBARRIER_EXPECT_TX(bar_base + b2 * 8, PHASE_TX);
    }

    // ---- weights: rows [seg*128, +128) of column jc, packed row-pairs ----
    // Ordering matches mainloop: k = src-block within segment, m = 4-float group.
    unsigned long long w2[64];
    {
        const float* wb = Wh + jc;
        #pragma unroll
        for (int k = 0; k < 2; k++)
            #pragma unroll
            for (int m = 0; m < 32; m++) {
                int r = seg * 128 + k * 64 + 2 * m;
                w2[k * 32 + m] = packf2(wb[(size_t)r * K_SZ],
                                        wb[(size_t)(r + 1) * K_SZ]);
            }
    }
    // zero all h buffers (incl. padding)
    for (int i = tid; i < 2 * 2 * CLUSTER_N * BLK_F; i += THREADS_RNN)
        (&sm.h[0][0][0][0])[i] = 0.f;

    // ---- x in registers: lanes 16..23 hold col w*8+(lane-16) for both dirs ----
    const bool xlane = (lane >= 16 && lane < 24);
    const int  xcol  = jg + w * 8 + (lane - 16);
    float xF[2] = {0.f, 0.f}, xR[2] = {0.f, 0.f};
    int   tF[2] = {0, 0},     tR[2] = {0, 0};
    if (xlane) {
        #pragma unroll
        for (int g = 0; g < 2; g++) {
            int gg = cid * 2 + g;
            xF[g] = g_P[(size_t)g_idx[0 * G_SZ + gg] * K_SZ + xcol];
            xR[g] = g_P[(size_t)g_idx[(T_STEPS - 2) * G_SZ + gg] * K_SZ + xcol];
            tF[g] = g_idx[1 * G_SZ + gg];
            tR[g] = g_idx[(T_STEPS - 3) * G_SZ + gg];
        }
    }
    __syncthreads();
    cluster.sync();   // barriers armed cluster-wide before any copies fly

    // issuer threads (tid 0..6): destination rank skipping self
    uint32_t rem_h_t = 0, rem_bar_t = 0;
    const uint32_t my_h = s2u(&sm.h[0][0][0][0]);
    if (tid < CLUSTER_N - 1) {
        int dst = tid + (tid >= rank ? 1 : 0);
        asm("mapa.shared::cluster.u32 %0, %1, %2;" : "=r"(rem_h_t)   : "r"(my_h),     "r"(dst));
        asm("mapa.shared::cluster.u32 %0, %1, %2;" : "=r"(rem_bar_t) : "r"(bar_base), "r"(dst));
    }

    const size_t hb0 = (size_t)T_STEPS * G_SZ * 2 * K_SZ;
    int p = 0;
    for (int s = 0; s < T_STEPS; s++) {
        const bool last = (s == T_STEPS - 1);
        const int np = p ^ 1;
        const int wpar = ((s >> 1) + 1 - (s & 1)) & 1;

        #pragma unroll
        for (int g = 0; g < 2; g++) {
            const int gg = cid * 2 + g;

            // ---- issue x gathers for step s+1 (hidden under mainloop) ----
            float xFn = 0.f, xRn = 0.f;
            if (xlane && !last) {
                xFn = g_P[(size_t)tF[g] * K_SZ + xcol];
                xRn = g_P[(size_t)tR[g] * K_SZ + xcol];
            }

            // ---- wait for this group's h (remote 3584B); re-arm next phase ----
            const uint32_t mybar = bar_base + (uint32_t)((g * 2 + p) * 8);
            if (s > 0) {
                MBARRIER_WAIT_PARITY(mybar, wpar);
                if (tid == 0 && s + 2 < T_STEPS)
                    MBARRIER_EXPECT_TX(mybar, PHASE_TX);
            }

            // ---- mainloop: rows [seg*128,+128) of col jc, both recs ----
            // segment seg = src blocks (2*seg) and (2*seg+1), each 132 floats.
            const float* hgb = &sm.h[g][p][0][0];
            unsigned long long a0e = 0ull, a0o = 0ull, a1e = 0ull, a1o = 0ull;
            #pragma unroll
            for (int k = 0; k < 2; k++) {
                const float* b0 = hgb + (2 * seg + k) * BLK_F;   // rec0 base
                const float* b1 = b0 + 64;                       // rec1 base
                #pragma unroll
                for (int m = 0; m < 16; m++) {
                    ulonglong2 H0 = *(const ulonglong2*)(b0 + 4 * m);
                    ulonglong2 H1 = *(const ulonglong2*)(b1 + 4 * m);
                    ffma2(a0e, H0.x, w2[k * 32 + 2 * m]);
                    ffma2(a0o, H0.y, w2[k * 32 + 2 * m + 1]);
                    ffma2(a1e, H1.x, w2[k * 32 + 2 * m]);
                    ffma2(a1o, H1.y, w2[k * 32 + 2 * m + 1]);
                }
            }
            float a0 = sum2(a0e) + sum2(a0o);
            float a1 = sum2(a1e) + sum2(a1o);
            a0 += __shfl_xor_sync(0xffffffffu, a0, 8);
            a0 += __shfl_xor_sync(0xffffffffu, a0, 16);
            a1 += __shfl_xor_sync(0xffffffffu, a1, 8);
            a1 += __shfl_xor_sync(0xffffffffu, a1, 16);

            float sxF = __shfl_sync(0xffffffffu, xF[g], 16 + (lane & 7));
            float sxR = __shfl_sync(0xffffffffu, xR[g], 16 + (lane & 7));

            float v0 = 0.f, v1 = 0.f;
            if (lane < 8) {
                v0 = tanhf(a0 + sxF);
                v1 = tanhf(a1 + sxR);
                if (!last) {
                    // local slice write: block src=rank, [rec0 | rec1]
                    float* dstp = &sm.h[g][np][rank][0];
                    dstp[w * 8 + lane]      = v0;
                    dstp[64 + w * 8 + lane] = v1;
                    asm volatile("fence.proxy.async.shared::cta;" ::: "memory");
                }
            }
            __syncthreads();

            // ---- 7 consolidated remote copies (512B each) ----
            if (!last && tid < CLUSTER_N - 1) {
                uint32_t off = (uint32_t)(((g * 2 + np) * CLUSTER_N + rank) * (BLK_F * 4));
                uint32_t rb  = rem_bar_t + (uint32_t)((g * 2 + np) * 8);
                asm volatile(
                    "cp.async.bulk.shared::cluster.shared::cta.mbarrier::complete_tx::bytes "
                    "[%0], [%1], %2, [%3];"
                    :: "r"(rem_h_t + off), "r"(my_h + off), "r"(SLICE_B), "r"(rb) : "memory");
            }

            // ---- tail: global out stores + x register rotation ----
            if (lane < 8) {
                int tt0 = tpos(s, 0), tt1 = tpos(s, 1);
                out[((size_t)tt0 * G_SZ + gg) * (2 * K_SZ) + jc]        = v0;
                out[((size_t)tt1 * G_SZ + gg) * (2 * K_SZ) + K_SZ + jc] = v1;
                if (last && writeHt) {
                    out[hb0 + (size_t)gg * (2 * K_SZ) + jc]        = v0;
                    out[hb0 + (size_t)gg * (2 * K_SZ) + K_SZ + jc] = v1;
                }
            } else if (xlane) {
                xF[g] = xFn;  xR[g] = xRn;
                if (s + 2 < T_STEPS) {
                    tF[g] = g_idx[tpos(s + 2, 0) * G_SZ + gg];
                    tR[g] = g_idx[tpos(s + 2, 1) * G_SZ + gg];
                }
            }
        }
        p = np;
    }
    cluster.sync();   // no CTA exits while peer copies may be in flight
}

// ---------------------------------------------------------------------------
extern "C" void kernel_launch(void* const* d_in, const int* in_sizes, int n_in,
                              void* d_out, int out_size) {
    const float* seq   = (const float*)d_in[0];  // (T, V)
    const int*   perms = (const int*)  d_in[1];  // (G, V)
    const float* We    = (const float*)d_in[2];  // (V, K)
    const float* Wx    = (const float*)d_in[3];  // (K, K)
    const float* Wh    = (const float*)d_in[4];  // (K, K)
    const float* b     = (const float*)d_in[5];  // (K,)
    float* out = (float*)d_out;
    (void)in_sizes; (void)n_in;

    long long need = (long long)T_STEPS * G_SZ * 2 * K_SZ + (long long)G_SZ * 2 * K_SZ;
    int writeHt = ((long long)out_size >= need) ? 1 : 0;

    dim3 ggrid(K_SZ / 64, V_SZ / 64);   // (8, 32) = 256 blocks
    prep_kernel<<<ggrid, 256>>>(seq, perms, We, Wx, b);
    rnn_kernel<<<NBLOCKS, THREADS_RNN>>>(Wh, out, writeHt);
}